// round 3
// baseline (speedup 1.0000x reference)
#include <cuda_runtime.h>
#include <mma.h>
#include <cstdint>

using namespace nvcuda;

// Problem constants (fixed by the dataset)
#define Bc 4
#define Qc 4096
#define Cc 256
#define Mh 8
#define Lc 4
#define Pc 4
#define Dc 32
#define Nc 21760
#define BQ (Bc*Qc)          // 16384

// Scratch (device globals; allocation-free rule)
__device__ float g_vp[(size_t)Bc*Mh*Nc*Dc];   // [B,M,N,D] head-major value proj
__device__ float g_qout[(size_t)BQ*384];      // fused [logits(128) | offsets(256)]
__device__ float g_heads[(size_t)BQ*256];     // sampled [BQ, C]
__device__ float g_wq[256*384];               // concat weights [C, 384]
__device__ float g_bq[384];                   // concat bias

// ---------------------------------------------------------------------------
// Concat W_attn|W_off (and biases) into g_wq / g_bq. <<<256, 384>>>
// ---------------------------------------------------------------------------
__global__ void concat_qw(const float* __restrict__ Wa, const float* __restrict__ Wo,
                          const float* __restrict__ ba, const float* __restrict__ bo) {
    const int r = blockIdx.x;      // 0..255
    const int c = threadIdx.x;     // 0..383
    g_wq[r * 384 + c] = (c < 128) ? Wa[r * 128 + c] : Wo[r * 256 + (c - 128)];
    if (r == 0) g_bq[c] = (c < 128) ? ba[c] : bo[c - 128];
}

// ---------------------------------------------------------------------------
// Tensor-core tf32 GEMM: C[Md,Nd] = A[Md,K] @ B[K,Nd] + bias[Nd]
// BM=128, BN=128, BK=32. 256 threads = 8 warps (4 row x 2 col), each warp
// 32x64 via 2x4 wmma m16n16k8 frags. Bias preloaded into accumulators from a
// replicated smem tile; direct frag store epilogue.
// SPLIT=1: 3xTF32 error-compensated (hi/lo split; hh+hl+lh).
// STORE_MODE 0: row-major. 1: permuted -> g_vp[B,M,N,D].
// ---------------------------------------------------------------------------
template<int SPLIT, int STORE_MODE>
__global__ __launch_bounds__(256, 1)
void gemm_tc(const float* __restrict__ A, const float* __restrict__ Bm,
             const float* __restrict__ bias, float* __restrict__ Cd,
             int Nd, int K) {
    constexpr int BM = 128, BN = 128, BK = 32;
    constexpr int BKp = 40;                // A smem row pitch
    constexpr int BNp = 136;               // B smem row pitch
    constexpr int ASZ = BM * BKp;          // 5120
    constexpr int BSZ = BK * BNp;          // 4352

    extern __shared__ float smem[];
    float* As_hi = smem;
    float* As_lo = As_hi + ASZ;                              // if SPLIT
    float* Bs_hi = smem + (SPLIT ? 2 : 1) * ASZ;
    float* Bs_lo = Bs_hi + BSZ;                              // if SPLIT
    float* biasS = Bs_hi + (SPLIT ? 2 : 1) * BSZ;            // 16 x BNp

    const int tid = threadIdx.x;
    const int wid = tid >> 5;
    const int warpRow = (wid >> 1) * 32;   // 0,32,64,96
    const int warpCol = (wid & 1) * 64;    // 0,64
    const int rowBase = blockIdx.y * BM;
    const int colBase = blockIdx.x * BN;

    // ---- bias -> replicated smem tile -> accumulators ----
    #pragma unroll
    for (int i = tid; i < 16 * BN; i += 256) {
        int r = i >> 7, c = i & 127;
        biasS[r * BNp + c] = bias[colBase + c];
    }
    __syncthreads();

    wmma::fragment<wmma::accumulator, 16, 16, 8, float> acc[2][4];
    #pragma unroll
    for (int i = 0; i < 2; i++)
        #pragma unroll
        for (int j = 0; j < 4; j++)
            wmma::load_matrix_sync(acc[i][j], &biasS[warpCol + j * 16], BNp,
                                   wmma::mem_row_major);
    __syncthreads();

    float4 ra[4], rb[4];
    // prefetch k0 = 0
    #pragma unroll
    for (int i = 0; i < 4; i++) {
        int lin = tid + i * 256;
        int r = lin >> 3, cv = (lin & 7) * 4;
        ra[i] = *(const float4*)(A + (size_t)(rowBase + r) * K + cv);
    }
    #pragma unroll
    for (int i = 0; i < 4; i++) {
        int lin = tid + i * 256;
        int r = lin >> 5, cv = (lin & 31) * 4;
        rb[i] = *(const float4*)(Bm + (size_t)r * Nd + colBase + cv);
    }

    for (int k0 = 0; k0 < K; k0 += BK) {
        // store prefetched tile to smem (with tf32 hi/lo conversion)
        #pragma unroll
        for (int i = 0; i < 4; i++) {
            int lin = tid + i * 256;
            int r = lin >> 3, cv = (lin & 7) * 4;
            float4 v = ra[i];
            float h;
            h = wmma::__float_to_tf32(v.x); As_hi[r*BKp+cv+0] = h; if (SPLIT) As_lo[r*BKp+cv+0] = wmma::__float_to_tf32(v.x - h);
            h = wmma::__float_to_tf32(v.y); As_hi[r*BKp+cv+1] = h; if (SPLIT) As_lo[r*BKp+cv+1] = wmma::__float_to_tf32(v.y - h);
            h = wmma::__float_to_tf32(v.z); As_hi[r*BKp+cv+2] = h; if (SPLIT) As_lo[r*BKp+cv+2] = wmma::__float_to_tf32(v.z - h);
            h = wmma::__float_to_tf32(v.w); As_hi[r*BKp+cv+3] = h; if (SPLIT) As_lo[r*BKp+cv+3] = wmma::__float_to_tf32(v.w - h);
        }
        #pragma unroll
        for (int i = 0; i < 4; i++) {
            int lin = tid + i * 256;
            int r = lin >> 5, cv = (lin & 31) * 4;
            float4 v = rb[i];
            float h;
            h = wmma::__float_to_tf32(v.x); Bs_hi[r*BNp+cv+0] = h; if (SPLIT) Bs_lo[r*BNp+cv+0] = wmma::__float_to_tf32(v.x - h);
            h = wmma::__float_to_tf32(v.y); Bs_hi[r*BNp+cv+1] = h; if (SPLIT) Bs_lo[r*BNp+cv+1] = wmma::__float_to_tf32(v.y - h);
            h = wmma::__float_to_tf32(v.z); Bs_hi[r*BNp+cv+2] = h; if (SPLIT) Bs_lo[r*BNp+cv+2] = wmma::__float_to_tf32(v.z - h);
            h = wmma::__float_to_tf32(v.w); Bs_hi[r*BNp+cv+3] = h; if (SPLIT) Bs_lo[r*BNp+cv+3] = wmma::__float_to_tf32(v.w - h);
        }
        __syncthreads();

        // prefetch next k-tile (non-split only; split saves regs)
        if (!SPLIT && k0 + BK < K) {
            #pragma unroll
            for (int i = 0; i < 4; i++) {
                int lin = tid + i * 256;
                int r = lin >> 3, cv = (lin & 7) * 4;
                ra[i] = *(const float4*)(A + (size_t)(rowBase + r) * K + k0 + BK + cv);
            }
            #pragma unroll
            for (int i = 0; i < 4; i++) {
                int lin = tid + i * 256;
                int r = lin >> 5, cv = (lin & 31) * 4;
                rb[i] = *(const float4*)(Bm + (size_t)(k0 + BK + r) * Nd + colBase + cv);
            }
        }

        #pragma unroll
        for (int kk = 0; kk < BK; kk += 8) {
            wmma::fragment<wmma::matrix_a, 16, 16, 8, wmma::precision::tf32, wmma::row_major> ah[2];
            wmma::fragment<wmma::matrix_b, 16, 16, 8, wmma::precision::tf32, wmma::row_major> bh[4];
            #pragma unroll
            for (int i = 0; i < 2; i++)
                wmma::load_matrix_sync(ah[i], &As_hi[(warpRow + i*16)*BKp + kk], BKp);
            #pragma unroll
            for (int j = 0; j < 4; j++)
                wmma::load_matrix_sync(bh[j], &Bs_hi[kk*BNp + warpCol + j*16], BNp);
            #pragma unroll
            for (int i = 0; i < 2; i++)
                #pragma unroll
                for (int j = 0; j < 4; j++)
                    wmma::mma_sync(acc[i][j], ah[i], bh[j], acc[i][j]);
            if (SPLIT) {
                wmma::fragment<wmma::matrix_a, 16, 16, 8, wmma::precision::tf32, wmma::row_major> al[2];
                wmma::fragment<wmma::matrix_b, 16, 16, 8, wmma::precision::tf32, wmma::row_major> bl[4];
                #pragma unroll
                for (int i = 0; i < 2; i++)
                    wmma::load_matrix_sync(al[i], &As_lo[(warpRow + i*16)*BKp + kk], BKp);
                #pragma unroll
                for (int j = 0; j < 4; j++)
                    wmma::load_matrix_sync(bl[j], &Bs_lo[kk*BNp + warpCol + j*16], BNp);
                #pragma unroll
                for (int i = 0; i < 2; i++)
                    #pragma unroll
                    for (int j = 0; j < 4; j++) {
                        wmma::mma_sync(acc[i][j], ah[i], bl[j], acc[i][j]);
                        wmma::mma_sync(acc[i][j], al[i], bh[j], acc[i][j]);
                    }
            }
        }

        if (SPLIT && k0 + BK < K) {
            #pragma unroll
            for (int i = 0; i < 4; i++) {
                int lin = tid + i * 256;
                int r = lin >> 3, cv = (lin & 7) * 4;
                ra[i] = *(const float4*)(A + (size_t)(rowBase + r) * K + k0 + BK + cv);
            }
            #pragma unroll
            for (int i = 0; i < 4; i++) {
                int lin = tid + i * 256;
                int r = lin >> 5, cv = (lin & 31) * 4;
                rb[i] = *(const float4*)(Bm + (size_t)(k0 + BK + r) * Nd + colBase + cv);
            }
        }
        __syncthreads();
    }

    // ---- epilogue: direct fragment stores ----
    #pragma unroll
    for (int i = 0; i < 2; i++) {
        int row0 = rowBase + warpRow + i * 16;
        #pragma unroll
        for (int j = 0; j < 4; j++) {
            int col0 = colBase + warpCol + j * 16;
            if (STORE_MODE == 0) {
                wmma::store_matrix_sync(Cd + (size_t)row0 * Nd + col0, acc[i][j],
                                        Nd, wmma::mem_row_major);
            } else {
                // row0 = b*Nc + n0 (tile never crosses b: Nc % 128 == 0)
                // col0 = m*32 + d0 (16-col tile never crosses a head)
                int b = row0 / Nc, n0 = row0 - b * Nc;
                int m = col0 >> 5, d0 = col0 & 31;
                float* ptr = Cd + ((((size_t)b * Mh + m) * Nc) + n0) * Dc + d0;
                wmma::store_matrix_sync(ptr, acc[i][j], Dc, wmma::mem_row_major);
            }
        }
    }
}

// ---------------------------------------------------------------------------
// Warp-autonomous sampling: one warp per (b,q,head). lane=channel d.
// Per-point bilinear params computed once on lane==pt (lanes 0..15), then
// consumer loop: 7 shuffles + 4 clamped loads (validity-zeroed weights).
// ---------------------------------------------------------------------------
__global__ void sample_kernel(const float* __restrict__ p,
                              const int* __restrict__ shapes,
                              const int* __restrict__ level_index) {
    const unsigned FULL = 0xffffffffu;
    const int w = (blockIdx.x * blockDim.x + threadIdx.x) >> 5;
    const int lane = threadIdx.x & 31;
    const int bq = w >> 3;
    const int m = w & 7;
    const int b = bq >> 12;

    // lane i holds off element m*32+i (fused buffer: offsets start at col 128)
    const float offv = g_qout[bq * 384 + 128 + m * 32 + lane];

    // softmax over 16 logits (lanes 0..15)
    float lg = (lane < 16) ? g_qout[bq * 384 + m * 16 + lane] : -1e30f;
    float mx = lg;
    #pragma unroll
    for (int s = 8; s; s >>= 1) mx = fmaxf(mx, __shfl_xor_sync(FULL, mx, s));
    float e = (lane < 16) ? __expf(lg - mx) : 0.f;
    float sum = e;
    #pragma unroll
    for (int s = 8; s; s >>= 1) sum += __shfl_xor_sync(FULL, sum, s);
    const float aw = e / sum;   // valid on lanes 0..15

    // ---- per-point precompute on lane = pt (lanes 0..15; others garbage) ----
    const int l = (lane >> 2) & 3;
    const int H  = shapes[2*l + 0];
    const int Wd = shapes[2*l + 1];
    const float px = p[bq * 8 + 2*l + 0];
    const float py = p[bq * 8 + 2*l + 1];
    const int base = level_index[l];

    const float ox = __shfl_sync(FULL, offv, (lane * 2) & 31);
    const float oy = __shfl_sync(FULL, offv, (lane * 2 + 1) & 31);

    const float x = fmaf(px, (float)Wd, ox) - 0.5f;
    const float y = fmaf(py, (float)H,  oy) - 0.5f;
    const float x0f = floorf(x), y0f = floorf(y);
    const float lx = x - x0f, ly = y - y0f;
    const int x0 = (int)x0f, y0 = (int)y0f;

    const bool inx0 = (unsigned)x0       < (unsigned)Wd;
    const bool inx1 = (unsigned)(x0 + 1) < (unsigned)Wd;
    const bool iny0 = (unsigned)y0       < (unsigned)H;
    const bool iny1 = (unsigned)(y0 + 1) < (unsigned)H;

    float w11 = aw * lx * ly;
    float w10 = aw * lx - w11;
    float w01 = aw * ly - w11;
    float w00 = aw - w10 - w01 - w11;
    w00 = (inx0 & iny0) ? w00 : 0.f;
    w10 = (inx1 & iny0) ? w10 : 0.f;
    w01 = (inx0 & iny1) ? w01 : 0.f;
    w11 = (inx1 & iny1) ? w11 : 0.f;

    const int x0c = min(max(x0, 0), Wd - 1);
    const int x1c = min(max(x0 + 1, 0), Wd - 1);
    const int y0c = min(max(y0, 0), H - 1);
    const int y1c = min(max(y0 + 1, 0), H - 1);
    const int i00  = base + y0c * Wd + x0c;
    const int dx   = x1c - x0c;            // 0 or 1
    const int dyW  = (y1c - y0c) * Wd;     // 0 or Wd

    // ---- consumer loop ----
    const float* __restrict__ vpb = g_vp + ((size_t)((b * Mh + m) * Nc) << 5) + lane;
    float acc = 0.f;
    #pragma unroll
    for (int pt = 0; pt < 16; pt++) {
        const float cw0 = __shfl_sync(FULL, w00, pt);
        const float cw1 = __shfl_sync(FULL, w10, pt);
        const float cw2 = __shfl_sync(FULL, w01, pt);
        const float cw3 = __shfl_sync(FULL, w11, pt);
        const int ci  = __shfl_sync(FULL, i00, pt);
        const int cdx = __shfl_sync(FULL, dx, pt);
        const int cdy = __shfl_sync(FULL, dyW, pt);
        const float* p00 = vpb + (ci << 5);
        acc = fmaf(cw0, p00[0], acc);
        acc = fmaf(cw1, p00[cdx << 5], acc);
        acc = fmaf(cw2, p00[cdy << 5], acc);
        acc = fmaf(cw3, p00[(cdy + cdx) << 5], acc);
    }

    g_heads[bq * 256 + m * 32 + lane] = acc;
}

// ---------------------------------------------------------------------------
extern "C" void kernel_launch(void* const* d_in, const int* in_sizes, int n_in,
                              void* d_out, int out_size) {
    const float* q       = (const float*)d_in[0];
    const float* p       = (const float*)d_in[1];
    const float* v       = (const float*)d_in[2];
    const int*   shapes  = (const int*)d_in[3];
    const int*   lvl_idx = (const int*)d_in[4];
    const float* W_off   = (const float*)d_in[5];
    const float* b_off   = (const float*)d_in[6];
    const float* W_attn  = (const float*)d_in[7];
    const float* b_attn  = (const float*)d_in[8];
    const float* W_val   = (const float*)d_in[9];
    const float* b_val   = (const float*)d_in[10];
    const float* W_out   = (const float*)d_in[11];
    const float* b_out   = (const float*)d_in[12];
    float* out = (float*)d_out;

    float* vp;    cudaGetSymbolAddress((void**)&vp,    g_vp);
    float* qout;  cudaGetSymbolAddress((void**)&qout,  g_qout);
    float* heads; cudaGetSymbolAddress((void**)&heads, g_heads);
    float* wq;    cudaGetSymbolAddress((void**)&wq,    g_wq);
    float* bqv;   cudaGetSymbolAddress((void**)&bqv,   g_bq);

    constexpr int ASZ = 128 * 40, BSZ = 32 * 136, BIAS = 16 * 136;
    const int smem0 = (ASZ + BSZ + BIAS) * 4;           // 46.6 KB
    const int smem1 = (2 * (ASZ + BSZ) + BIAS) * 4;     // 84.5 KB
    static bool attr_done = false;
    if (!attr_done) {
        cudaFuncSetAttribute(gemm_tc<1, 0>, cudaFuncAttributeMaxDynamicSharedMemorySize, smem1);
        cudaFuncSetAttribute(gemm_tc<0, 0>, cudaFuncAttributeMaxDynamicSharedMemorySize, smem0);
        cudaFuncSetAttribute(gemm_tc<0, 1>, cudaFuncAttributeMaxDynamicSharedMemorySize, smem0);
        attr_done = true;
    }

    // 0) concat W_attn|W_off
    concat_qw<<<256, 384>>>(W_attn, W_off, b_attn, b_off);
    // 1) value projection: [B*N,256] @ [256,256] -> g_vp (head-major), tf32
    {
        dim3 grid(Cc / 128, (Bc * Nc) / 128);   // (2, 680)
        gemm_tc<0, 1><<<grid, 256, smem0>>>(v, W_val, b_val, vp, Cc, Cc);
    }
    // 2) fused logits+offsets: [BQ,256] @ [256,384], 3xTF32
    {
        dim3 grid(384 / 128, BQ / 128);         // (3, 128)
        gemm_tc<1, 0><<<grid, 256, smem1>>>(q, wq, bqv, qout, 384, Cc);
    }
    // 3) softmax + bilinear sampling -> g_heads (warp per (b,q,m))
    sample_kernel<<<(BQ * Mh) / 8, 256>>>(p, shapes, lvl_idx);
    // 4) output projection: [BQ,256] @ [256,256] -> d_out, tf32
    {
        dim3 grid(Cc / 128, BQ / 128);          // (2, 128)
        gemm_tc<0, 0><<<grid, 256, smem0>>>(heads, W_out, b_out, out, Cc, Cc);
    }
}

// round 5
// speedup vs baseline: 2.1994x; 2.1994x over previous
#include <cuda_runtime.h>
#include <cuda_fp16.h>
#include <mma.h>
#include <cstdint>

using namespace nvcuda;

// Problem constants (fixed by the dataset)
#define Bc 4
#define Qc 4096
#define Cc 256
#define Mh 8
#define Lc 4
#define Pc 4
#define Dc 32
#define Nc 21760
#define BQ (Bc*Qc)          // 16384

// Scratch (device globals; allocation-free rule)
__device__ float g_vp[(size_t)Bc*Mh*Nc*Dc];   // [B,M,N,D] head-major value proj
__device__ float g_qout[(size_t)BQ*384];      // fused [logits(128) | offsets(256)]
__device__ float g_heads[(size_t)BQ*256];     // sampled [BQ, C]
__device__ float g_wq[256*384];               // concat weights [C, 384]
__device__ float g_bq[384];                   // concat bias

// ---------------------------------------------------------------------------
// Concat W_attn|W_off (and biases) into g_wq / g_bq. <<<256, 384>>>
// ---------------------------------------------------------------------------
__global__ void concat_qw(const float* __restrict__ Wa, const float* __restrict__ Wo,
                          const float* __restrict__ ba, const float* __restrict__ bo) {
    const int r = blockIdx.x;
    const int c = threadIdx.x;
    g_wq[r * 384 + c] = (c < 128) ? Wa[r * 128 + c] : Wo[r * 256 + (c - 128)];
    if (r == 0) g_bq[c] = (c < 128) ? ba[c] : bo[c - 128];
}

__device__ __forceinline__ uint32_t pack_h2(float a, float b) {
    __half2 t = __floats2half2_rn(a, b);
    return *reinterpret_cast<uint32_t*>(&t);
}

// ---------------------------------------------------------------------------
// fp16 tensor-core GEMM: C[Md,Nd] = A[Md,256] @ B[256,Nd] + bias[Nd]
// BM=128, BN=128, BK=64. 256 threads = 8 warps (4 row x 2 col); each warp
// 32x64 via 2x4 wmma m16n16k16 half frags, fp32 accumulate.
// Bias preloaded into accumulators via replicated smem tile; direct frag
// store epilogue. STORE_MODE 0: row-major. 1: permuted -> g_vp[B,M,N,D].
// ---------------------------------------------------------------------------
template<int STORE_MODE>
__global__ __launch_bounds__(256)
void gemm_fp16(const float* __restrict__ A, const float* __restrict__ Bm,
               const float* __restrict__ bias, float* __restrict__ Cd, int Nd) {
    constexpr int BM = 128, BN = 128, BK = 64;
    constexpr int AKp = 72;                 // A smem pitch (halves)
    constexpr int BNp = 136;                // B smem pitch (halves)
    constexpr int ASZH = BM * AKp;          // 9216 halves
    constexpr int BSZH = BK * BNp;          // 8704 halves

    extern __shared__ __align__(16) char smem[];
    __half* As = (__half*)smem;                       // 18432 B
    __half* Bs = (__half*)(smem + ASZH * 2);          // 17408 B
    float*  biasS = (float*)(smem + ASZH * 2 + BSZH * 2);   // 16 x BNp floats

    const int tid = threadIdx.x;
    const int wid = tid >> 5;
    const int warpRow = (wid >> 1) * 32;   // 0,32,64,96
    const int warpCol = (wid & 1) * 64;    // 0,64
    const int rowBase = blockIdx.y * BM;
    const int colBase = blockIdx.x * BN;

    // ---- bias -> replicated smem tile (16 rows) -> accumulators ----
    #pragma unroll
    for (int i = tid; i < 16 * BN; i += 256) {
        int r = i >> 7, c = i & 127;
        biasS[r * BNp + c] = bias[colBase + c];
    }
    __syncthreads();

    wmma::fragment<wmma::accumulator, 16, 16, 16, float> acc[2][4];
    #pragma unroll
    for (int i = 0; i < 2; i++)
        #pragma unroll
        for (int j = 0; j < 4; j++)
            wmma::load_matrix_sync(acc[i][j], &biasS[warpCol + j * 16], BNp,
                                   wmma::mem_row_major);
    __syncthreads();

    for (int k0 = 0; k0 < Cc; k0 += BK) {
        // ---- A tile: 128 x 64 fp32 -> half. 2048 float4, 8/thread ----
        #pragma unroll
        for (int i = 0; i < 8; i++) {
            int idx = tid + i * 256;
            int r = idx >> 4, c4 = (idx & 15) * 4;
            float4 v = *(const float4*)(A + (size_t)(rowBase + r) * Cc + k0 + c4);
            *(uint2*)&As[r * AKp + c4] = make_uint2(pack_h2(v.x, v.y), pack_h2(v.z, v.w));
        }
        // ---- B tile: 64 x 128 fp32 -> half. 2048 float4, 8/thread ----
        #pragma unroll
        for (int i = 0; i < 8; i++) {
            int idx = tid + i * 256;
            int r = idx >> 5, c4 = (idx & 31) * 4;
            float4 v = *(const float4*)(Bm + (size_t)(k0 + r) * Nd + colBase + c4);
            *(uint2*)&Bs[r * BNp + c4] = make_uint2(pack_h2(v.x, v.y), pack_h2(v.z, v.w));
        }
        __syncthreads();

        #pragma unroll
        for (int kk = 0; kk < BK; kk += 16) {
            wmma::fragment<wmma::matrix_a, 16, 16, 16, __half, wmma::row_major> af[2];
            wmma::fragment<wmma::matrix_b, 16, 16, 16, __half, wmma::row_major> bf[4];
            #pragma unroll
            for (int i = 0; i < 2; i++)
                wmma::load_matrix_sync(af[i], &As[(warpRow + i * 16) * AKp + kk], AKp);
            #pragma unroll
            for (int j = 0; j < 4; j++)
                wmma::load_matrix_sync(bf[j], &Bs[kk * BNp + warpCol + j * 16], BNp);
            #pragma unroll
            for (int i = 0; i < 2; i++)
                #pragma unroll
                for (int j = 0; j < 4; j++)
                    wmma::mma_sync(acc[i][j], af[i], bf[j], acc[i][j]);
        }
        __syncthreads();
    }

    // ---- epilogue: direct fragment stores ----
    #pragma unroll
    for (int i = 0; i < 2; i++) {
        int row0 = rowBase + warpRow + i * 16;
        #pragma unroll
        for (int j = 0; j < 4; j++) {
            int col0 = colBase + warpCol + j * 16;
            if (STORE_MODE == 0) {
                wmma::store_matrix_sync(Cd + (size_t)row0 * Nd + col0, acc[i][j],
                                        Nd, wmma::mem_row_major);
            } else {
                // row0 = b*Nc + n0 (tile never crosses b: Nc % 128 == 0)
                // col0 = m*32 + d0 (16-col tile never crosses a head)
                int b = row0 / Nc, n0 = row0 - b * Nc;
                int m = col0 >> 5, d0 = col0 & 31;
                float* ptr = Cd + ((((size_t)b * Mh + m) * Nc) + n0) * Dc + d0;
                wmma::store_matrix_sync(ptr, acc[i][j], Dc, wmma::mem_row_major);
            }
        }
    }
}

// ---------------------------------------------------------------------------
// Warp-autonomous sampling: one warp per (b,q,head). lane=channel d.
// Per-point bilinear params computed once on lane==pt (lanes 0..15), then
// consumer loop: 7 shuffles + 4 clamped loads (validity-zeroed weights).
// ---------------------------------------------------------------------------
__global__ void sample_kernel(const float* __restrict__ p,
                              const int* __restrict__ shapes,
                              const int* __restrict__ level_index) {
    const unsigned FULL = 0xffffffffu;
    const int w = (blockIdx.x * blockDim.x + threadIdx.x) >> 5;
    const int lane = threadIdx.x & 31;
    const int bq = w >> 3;
    const int m = w & 7;
    const int b = bq >> 12;

    const float offv = g_qout[bq * 384 + 128 + m * 32 + lane];

    float lg = (lane < 16) ? g_qout[bq * 384 + m * 16 + lane] : -1e30f;
    float mx = lg;
    #pragma unroll
    for (int s = 8; s; s >>= 1) mx = fmaxf(mx, __shfl_xor_sync(FULL, mx, s));
    float e = (lane < 16) ? __expf(lg - mx) : 0.f;
    float sum = e;
    #pragma unroll
    for (int s = 8; s; s >>= 1) sum += __shfl_xor_sync(FULL, sum, s);
    const float aw = e / sum;

    // per-point precompute on lane = pt (lanes 0..15)
    const int l = (lane >> 2) & 3;
    const int H  = shapes[2*l + 0];
    const int Wd = shapes[2*l + 1];
    const float px = p[bq * 8 + 2*l + 0];
    const float py = p[bq * 8 + 2*l + 1];
    const int base = level_index[l];

    const float ox = __shfl_sync(FULL, offv, (lane * 2) & 31);
    const float oy = __shfl_sync(FULL, offv, (lane * 2 + 1) & 31);

    const float x = fmaf(px, (float)Wd, ox) - 0.5f;
    const float y = fmaf(py, (float)H,  oy) - 0.5f;
    const float x0f = floorf(x), y0f = floorf(y);
    const float lx = x - x0f, ly = y - y0f;
    const int x0 = (int)x0f, y0 = (int)y0f;

    const bool inx0 = (unsigned)x0       < (unsigned)Wd;
    const bool inx1 = (unsigned)(x0 + 1) < (unsigned)Wd;
    const bool iny0 = (unsigned)y0       < (unsigned)H;
    const bool iny1 = (unsigned)(y0 + 1) < (unsigned)H;

    float w11 = aw * lx * ly;
    float w10 = aw * lx - w11;
    float w01 = aw * ly - w11;
    float w00 = aw - w10 - w01 - w11;
    w00 = (inx0 & iny0) ? w00 : 0.f;
    w10 = (inx1 & iny0) ? w10 : 0.f;
    w01 = (inx0 & iny1) ? w01 : 0.f;
    w11 = (inx1 & iny1) ? w11 : 0.f;

    const int x0c = min(max(x0, 0), Wd - 1);
    const int x1c = min(max(x0 + 1, 0), Wd - 1);
    const int y0c = min(max(y0, 0), H - 1);
    const int y1c = min(max(y0 + 1, 0), H - 1);
    const int i00 = base + y0c * Wd + x0c;
    const int dx  = x1c - x0c;            // 0 or 1
    const int dyW = (y1c - y0c) * Wd;     // 0 or Wd

    const float* __restrict__ vpb = g_vp + ((size_t)((b * Mh + m) * Nc) << 5) + lane;
    float acc = 0.f;
    #pragma unroll
    for (int pt = 0; pt < 16; pt++) {
        const float cw0 = __shfl_sync(FULL, w00, pt);
        const float cw1 = __shfl_sync(FULL, w10, pt);
        const float cw2 = __shfl_sync(FULL, w01, pt);
        const float cw3 = __shfl_sync(FULL, w11, pt);
        const int ci  = __shfl_sync(FULL, i00, pt);
        const int cdx = __shfl_sync(FULL, dx, pt);
        const int cdy = __shfl_sync(FULL, dyW, pt);
        const float* p00 = vpb + (ci << 5);
        acc = fmaf(cw0, p00[0], acc);
        acc = fmaf(cw1, p00[cdx << 5], acc);
        acc = fmaf(cw2, p00[cdy << 5], acc);
        acc = fmaf(cw3, p00[(cdy + cdx) << 5], acc);
    }

    g_heads[bq * 256 + m * 32 + lane] = acc;
}

// ---------------------------------------------------------------------------
extern "C" void kernel_launch(void* const* d_in, const int* in_sizes, int n_in,
                              void* d_out, int out_size) {
    const float* q       = (const float*)d_in[0];
    const float* p       = (const float*)d_in[1];
    const float* v       = (const float*)d_in[2];
    const int*   shapes  = (const int*)d_in[3];
    const int*   lvl_idx = (const int*)d_in[4];
    const float* W_off   = (const float*)d_in[5];
    const float* b_off   = (const float*)d_in[6];
    const float* W_attn  = (const float*)d_in[7];
    const float* b_attn  = (const float*)d_in[8];
    const float* W_val   = (const float*)d_in[9];
    const float* b_val   = (const float*)d_in[10];
    const float* W_out   = (const float*)d_in[11];
    const float* b_out   = (const float*)d_in[12];
    float* out = (float*)d_out;

    float* vp;    cudaGetSymbolAddress((void**)&vp,    g_vp);
    float* qout;  cudaGetSymbolAddress((void**)&qout,  g_qout);
    float* heads; cudaGetSymbolAddress((void**)&heads, g_heads);
    float* wq;    cudaGetSymbolAddress((void**)&wq,    g_wq);
    float* bqv;   cudaGetSymbolAddress((void**)&bqv,   g_bq);

    // smem: A(18432B) + B(17408B) + bias(16*136*4=8704B) = 44544 B
    const int smemB = 128 * 72 * 2 + 64 * 136 * 2 + 16 * 136 * 4;
    cudaFuncSetAttribute(gemm_fp16<0>, cudaFuncAttributeMaxDynamicSharedMemorySize, smemB);
    cudaFuncSetAttribute(gemm_fp16<1>, cudaFuncAttributeMaxDynamicSharedMemorySize, smemB);

    // 0) concat W_attn|W_off
    concat_qw<<<256, 384>>>(W_attn, W_off, b_attn, b_off);
    // 1) value projection: [B*N,256] @ [256,256] -> g_vp (head-major), fp16 TC
    {
        dim3 grid(Cc / 128, (Bc * Nc) / 128);   // (2, 680)
        gemm_fp16<1><<<grid, 256, smemB>>>(v, W_val, b_val, vp, Cc);
    }
    // 2) fused logits+offsets: [BQ,256] @ [256,384], fp16 TC
    {
        dim3 grid(384 / 128, BQ / 128);         // (3, 128)
        gemm_fp16<0><<<grid, 256, smemB>>>(q, wq, bqv, qout, 384);
    }
    // 3) softmax + bilinear sampling -> g_heads (warp per (b,q,m))
    sample_kernel<<<(BQ * Mh) / 8, 256>>>(p, shapes, lvl_idx);
    // 4) output projection: [BQ,256] @ [256,256] -> d_out, fp16 TC
    {
        dim3 grid(Cc / 128, BQ / 128);          // (2, 128)
        gemm_fp16<0><<<grid, 256, smemB>>>(heads, W_out, b_out, out, Cc);
    }
}

// round 6
// speedup vs baseline: 2.4692x; 1.1226x over previous
#include <cuda_runtime.h>
#include <cuda_fp16.h>
#include <mma.h>
#include <cstdint>

using namespace nvcuda;

// Problem constants (fixed by the dataset)
#define Bc 4
#define Qc 4096
#define Cc 256
#define Mh 8
#define Lc 4
#define Pc 4
#define Dc 32
#define Nc 21760
#define BQ (Bc*Qc)          // 16384

// Scratch (device globals; allocation-free rule)
__device__ __half g_vph[(size_t)Bc*Mh*Nc*Dc]; // [B,M,N,D] head-major vproj, fp16
__device__ float g_qout[(size_t)BQ*384];      // fused [logits(128) | offsets(256)]
__device__ float g_heads[(size_t)BQ*256];     // sampled [BQ, C]
__device__ float g_wq[256*384];               // concat weights [C, 384]
__device__ float g_bq[384];                   // concat bias

// ---------------------------------------------------------------------------
// Concat W_attn|W_off (and biases) into g_wq / g_bq. <<<256, 384>>>
// ---------------------------------------------------------------------------
__global__ void concat_qw(const float* __restrict__ Wa, const float* __restrict__ Wo,
                          const float* __restrict__ ba, const float* __restrict__ bo) {
    const int r = blockIdx.x;
    const int c = threadIdx.x;
    g_wq[r * 384 + c] = (c < 128) ? Wa[r * 128 + c] : Wo[r * 256 + (c - 128)];
    if (r == 0) g_bq[c] = (c < 128) ? ba[c] : bo[c - 128];
}

__device__ __forceinline__ uint32_t pack_h2(float a, float b) {
    __half2 t = __floats2half2_rn(a, b);
    return *reinterpret_cast<uint32_t*>(&t);
}

// ---------------------------------------------------------------------------
// fp16 tensor-core GEMM: C[Md,Nd] = A[Md,256] @ B[256,Nd] + bias[Nd]
// BM=128, BN=128, BK=64. 256 threads = 8 warps (4 row x 2 col); each warp
// 32x64 via 2x4 wmma m16n16k16 half frags, fp32 accumulate. Bias preloaded
// into accumulators via replicated smem tile.
// STORE_MODE 0: row-major fp32 store (direct frag stores).
// STORE_MODE 1: permuted fp16 store -> g_vph[B,M,N,D] (staged via smem).
// ---------------------------------------------------------------------------
template<int STORE_MODE>
__global__ __launch_bounds__(256)
void gemm_fp16(const float* __restrict__ A, const float* __restrict__ Bm,
               const float* __restrict__ bias, float* __restrict__ Cd, int Nd) {
    constexpr int BM = 128, BN = 128, BK = 64;
    constexpr int AKp = 72;                 // A smem pitch (halves)
    constexpr int BNp = 136;                // B smem pitch (halves)
    constexpr int ASZH = BM * AKp;          // 9216 halves
    constexpr int BSZH = BK * BNp;          // 8704 halves

    extern __shared__ __align__(16) char smem[];
    __half* As = (__half*)smem;                       // 18432 B
    __half* Bs = (__half*)(smem + ASZH * 2);          // 17408 B
    float*  biasS = (float*)(smem + ASZH * 2 + BSZH * 2);   // 16 x BNp floats

    const int tid = threadIdx.x;
    const int wid = tid >> 5;
    const int warpRow = (wid >> 1) * 32;   // 0,32,64,96
    const int warpCol = (wid & 1) * 64;    // 0,64
    const int rowBase = blockIdx.y * BM;
    const int colBase = blockIdx.x * BN;

    // ---- bias -> replicated smem tile (16 rows) -> accumulators ----
    #pragma unroll
    for (int i = tid; i < 16 * BN; i += 256) {
        int r = i >> 7, c = i & 127;
        biasS[r * BNp + c] = bias[colBase + c];
    }
    __syncthreads();

    wmma::fragment<wmma::accumulator, 16, 16, 16, float> acc[2][4];
    #pragma unroll
    for (int i = 0; i < 2; i++)
        #pragma unroll
        for (int j = 0; j < 4; j++)
            wmma::load_matrix_sync(acc[i][j], &biasS[warpCol + j * 16], BNp,
                                   wmma::mem_row_major);
    __syncthreads();

    for (int k0 = 0; k0 < Cc; k0 += BK) {
        // ---- A tile: 128 x 64 fp32 -> half. 2048 float4, 8/thread ----
        #pragma unroll
        for (int i = 0; i < 8; i++) {
            int idx = tid + i * 256;
            int r = idx >> 4, c4 = (idx & 15) * 4;
            float4 v = *(const float4*)(A + (size_t)(rowBase + r) * Cc + k0 + c4);
            *(uint2*)&As[r * AKp + c4] = make_uint2(pack_h2(v.x, v.y), pack_h2(v.z, v.w));
        }
        // ---- B tile: 64 x 128 fp32 -> half. 2048 float4, 8/thread ----
        #pragma unroll
        for (int i = 0; i < 8; i++) {
            int idx = tid + i * 256;
            int r = idx >> 5, c4 = (idx & 31) * 4;
            float4 v = *(const float4*)(Bm + (size_t)(k0 + r) * Nd + colBase + c4);
            *(uint2*)&Bs[r * BNp + c4] = make_uint2(pack_h2(v.x, v.y), pack_h2(v.z, v.w));
        }
        __syncthreads();

        #pragma unroll
        for (int kk = 0; kk < BK; kk += 16) {
            wmma::fragment<wmma::matrix_a, 16, 16, 16, __half, wmma::row_major> af[2];
            wmma::fragment<wmma::matrix_b, 16, 16, 16, __half, wmma::row_major> bf[4];
            #pragma unroll
            for (int i = 0; i < 2; i++)
                wmma::load_matrix_sync(af[i], &As[(warpRow + i * 16) * AKp + kk], AKp);
            #pragma unroll
            for (int j = 0; j < 4; j++)
                wmma::load_matrix_sync(bf[j], &Bs[kk * BNp + warpCol + j * 16], BNp);
            #pragma unroll
            for (int i = 0; i < 2; i++)
                #pragma unroll
                for (int j = 0; j < 4; j++)
                    wmma::mma_sync(acc[i][j], af[i], bf[j], acc[i][j]);
        }
        __syncthreads();
    }

    if (STORE_MODE == 0) {
        // ---- direct fragment stores (fp32 row-major) ----
        #pragma unroll
        for (int i = 0; i < 2; i++) {
            int row0 = rowBase + warpRow + i * 16;
            #pragma unroll
            for (int j = 0; j < 4; j++) {
                int col0 = colBase + warpCol + j * 16;
                wmma::store_matrix_sync(Cd + (size_t)row0 * Nd + col0, acc[i][j],
                                        Nd, wmma::mem_row_major);
            }
        }
    } else {
        // ---- staged fp16 permuted store -> g_vph, two 64-col passes ----
        constexpr int SP = 68;                 // staging pitch (floats)
        float* stage = (float*)smem;           // 128*68*4 = 34816 B (fits)
        #pragma unroll
        for (int pass = 0; pass < 2; pass++) {
            __syncthreads();
            if ((wid & 1) == pass) {
                #pragma unroll
                for (int i = 0; i < 2; i++)
                    #pragma unroll
                    for (int j = 0; j < 4; j++)
                        wmma::store_matrix_sync(&stage[(warpRow + i * 16) * SP + j * 16],
                                                acc[i][j], SP, wmma::mem_row_major);
            }
            __syncthreads();
            // 128 rows x 64 cols -> half, permuted. 2048 uint2, 8/thread.
            #pragma unroll
            for (int i = 0; i < 8; i++) {
                int idx = tid + i * 256;
                int r = idx >> 4, c4 = (idx & 15) * 4;
                float4 v = *(const float4*)&stage[r * SP + c4];
                int row0 = rowBase + r;
                int colG = colBase + pass * 64 + c4;
                // row0 = b*Nc + n (tile never crosses b); colG = m*32 + d
                int b = row0 / Nc, n = row0 - b * Nc;
                int m = colG >> 5, d = colG & 31;
                __half* ptr = g_vph + (((size_t)((b * Mh + m) * Nc) + n) << 5) + d;
                *(uint2*)ptr = make_uint2(pack_h2(v.x, v.y), pack_h2(v.z, v.w));
            }
        }
    }
}

// ---------------------------------------------------------------------------
// Warp-autonomous sampling: one warp per (b,q,head).
// Precompute on all 32 lanes: lane = pt*2 + corner-group (group 0 = left
// corners x0, group 1 = right corners x0+1): weights (top/bottom) and row
// indices, validity-zeroed / clamped.
// Consumer loop: 4 shuffles + 2 paired-corner __half2 loads per point.
// Lanes 0-15 carry the left-corner contribution of channels (2 per lane),
// lanes 16-31 the right-corner contribution; one xor-16 reduce at the end.
// ---------------------------------------------------------------------------
__global__ void sample_kernel(const float* __restrict__ p,
                              const int* __restrict__ shapes,
                              const int* __restrict__ level_index) {
    const unsigned FULL = 0xffffffffu;
    const int w = (blockIdx.x * blockDim.x + threadIdx.x) >> 5;
    const int lane = threadIdx.x & 31;
    const int bq = w >> 3;
    const int m = w & 7;
    const int b = bq >> 12;

    const float offv = g_qout[bq * 384 + 128 + m * 32 + lane];

    // softmax over 16 logits (lanes 0..15)
    float lg = (lane < 16) ? g_qout[bq * 384 + m * 16 + lane] : -1e30f;
    float mx = lg;
    #pragma unroll
    for (int s = 8; s; s >>= 1) mx = fmaxf(mx, __shfl_xor_sync(FULL, mx, s));
    float e = (lane < 16) ? __expf(lg - mx) : 0.f;
    float sum = e;
    #pragma unroll
    for (int s = 8; s; s >>= 1) sum += __shfl_xor_sync(FULL, sum, s);
    const float awv = e / sum;   // valid on lanes 0..15

    // ---- per-(point, corner-group) precompute: lane = pt*2 + grp ----
    const int pt  = lane >> 1;
    const int grp = lane & 1;
    const int l = pt >> 2;
    const int H  = shapes[2*l + 0];
    const int Wd = shapes[2*l + 1];
    const float px = p[bq * 8 + 2*l + 0];
    const float py = p[bq * 8 + 2*l + 1];
    const int base = level_index[l];

    const float ox = __shfl_sync(FULL, offv, pt * 2);
    const float oy = __shfl_sync(FULL, offv, pt * 2 + 1);
    const float aw = __shfl_sync(FULL, awv, pt);

    const float x = fmaf(px, (float)Wd, ox) - 0.5f;
    const float y = fmaf(py, (float)H,  oy) - 0.5f;
    const float x0f = floorf(x), y0f = floorf(y);
    const float lx = x - x0f, ly = y - y0f;
    const int x0 = (int)x0f, y0 = (int)y0f;

    const bool inx0 = (unsigned)x0       < (unsigned)Wd;
    const bool inx1 = (unsigned)(x0 + 1) < (unsigned)Wd;
    const bool iny0 = (unsigned)y0       < (unsigned)H;
    const bool iny1 = (unsigned)(y0 + 1) < (unsigned)H;

    float w11 = aw * lx * ly;
    float w10 = aw * lx - w11;          // x1,y0
    float w01 = aw * ly - w11;          // x0,y1
    float w00 = aw - w10 - w01 - w11;   // x0,y0
    w00 = (inx0 & iny0) ? w00 : 0.f;
    w10 = (inx1 & iny0) ? w10 : 0.f;
    w01 = (inx0 & iny1) ? w01 : 0.f;
    w11 = (inx1 & iny1) ? w11 : 0.f;

    const int x0c = min(max(x0, 0), Wd - 1);
    const int x1c = min(max(x0 + 1, 0), Wd - 1);
    const int y0c = min(max(y0, 0), H - 1);
    const int y1c = min(max(y0 + 1, 0), H - 1);
    const int i00 = base + y0c * Wd + x0c;
    const int dx  = x1c - x0c;            // 0 or 1
    const int dyW = (y1c - y0c) * Wd;     // 0 or Wd

    const float wtop = grp ? w10 : w00;
    const float wbot = grp ? w11 : w01;
    const int   itop = i00 + dx * grp;
    const int   ibot = itop + dyW;

    // ---- consumer loop: this lane's corner group = lane>>4 ----
    const int myg = lane >> 4;
    const __half* __restrict__ vpb =
        g_vph + ((size_t)((b * Mh + m) * Nc) << 5) + (lane & 15) * 2;

    float accx = 0.f, accy = 0.f;
    #pragma unroll
    for (int q = 0; q < 16; q++) {
        const int src = q * 2 + myg;
        const float wt = __shfl_sync(FULL, wtop, src);
        const float wb = __shfl_sync(FULL, wbot, src);
        const int it = __shfl_sync(FULL, itop, src);
        const int ib = __shfl_sync(FULL, ibot, src);
        const float2 tv = __half22float2(*(const __half2*)(vpb + (it << 5)));
        const float2 bv = __half22float2(*(const __half2*)(vpb + (ib << 5)));
        accx = fmaf(wt, tv.x, fmaf(wb, bv.x, accx));
        accy = fmaf(wt, tv.y, fmaf(wb, bv.y, accy));
    }
    // combine left-group (lanes 0-15) + right-group (lanes 16-31)
    accx += __shfl_xor_sync(FULL, accx, 16);
    accy += __shfl_xor_sync(FULL, accy, 16);

    if (lane < 16)
        *(float2*)(g_heads + bq * 256 + m * 32 + lane * 2) = make_float2(accx, accy);
}

// ---------------------------------------------------------------------------
extern "C" void kernel_launch(void* const* d_in, const int* in_sizes, int n_in,
                              void* d_out, int out_size) {
    const float* q       = (const float*)d_in[0];
    const float* p       = (const float*)d_in[1];
    const float* v       = (const float*)d_in[2];
    const int*   shapes  = (const int*)d_in[3];
    const int*   lvl_idx = (const int*)d_in[4];
    const float* W_off   = (const float*)d_in[5];
    const float* b_off   = (const float*)d_in[6];
    const float* W_attn  = (const float*)d_in[7];
    const float* b_attn  = (const float*)d_in[8];
    const float* W_val   = (const float*)d_in[9];
    const float* b_val   = (const float*)d_in[10];
    const float* W_out   = (const float*)d_in[11];
    const float* b_out   = (const float*)d_in[12];
    float* out = (float*)d_out;

    float* qout;  cudaGetSymbolAddress((void**)&qout,  g_qout);
    float* heads; cudaGetSymbolAddress((void**)&heads, g_heads);
    float* wq;    cudaGetSymbolAddress((void**)&wq,    g_wq);
    float* bqv;   cudaGetSymbolAddress((void**)&bqv,   g_bq);

    // smem: A(18432B) + B(17408B) + bias(16*136*4=8704B) = 44544 B
    const int smemB = 128 * 72 * 2 + 64 * 136 * 2 + 16 * 136 * 4;
    cudaFuncSetAttribute(gemm_fp16<0>, cudaFuncAttributeMaxDynamicSharedMemorySize, smemB);
    cudaFuncSetAttribute(gemm_fp16<1>, cudaFuncAttributeMaxDynamicSharedMemorySize, smemB);

    // 0) concat W_attn|W_off
    concat_qw<<<256, 384>>>(W_attn, W_off, b_attn, b_off);
    // 1) value projection: [B*N,256] @ [256,256] -> g_vph (head-major fp16)
    {
        dim3 grid(Cc / 128, (Bc * Nc) / 128);   // (2, 680)
        gemm_fp16<1><<<grid, 256, smemB>>>(v, W_val, b_val, nullptr, Cc);
    }
    // 2) fused logits+offsets: [BQ,256] @ [256,384], fp16 TC
    {
        dim3 grid(384 / 128, BQ / 128);         // (3, 128)
        gemm_fp16<0><<<grid, 256, smemB>>>(q, wq, bqv, qout, 384);
    }
    // 3) softmax + bilinear sampling -> g_heads (warp per (b,q,m))
    sample_kernel<<<(BQ * Mh) / 8, 256>>>(p, shapes, lvl_idx);
    // 4) output projection: [BQ,256] @ [256,256] -> d_out, fp16 TC
    {
        dim3 grid(Cc / 128, BQ / 128);          // (2, 128)
        gemm_fp16<0><<<grid, 256, smemB>>>(heads, W_out, b_out, out, Cc);
    }
}

// round 7
// speedup vs baseline: 2.5842x; 1.0466x over previous
#include <cuda_runtime.h>
#include <cuda_fp16.h>
#include <mma.h>
#include <cstdint>

using namespace nvcuda;

// Problem constants (fixed by the dataset)
#define Bc 4
#define Qc 4096
#define Cc 256
#define Mh 8
#define Lc 4
#define Pc 4
#define Dc 32
#define Nc 21760
#define BQ (Bc*Qc)          // 16384

// Scratch (device globals; allocation-free rule)
__device__ __half g_vph[(size_t)Bc*Mh*Nc*Dc]; // [B,M,N,D] head-major vproj, fp16
__device__ __half g_vh[(size_t)Bc*Nc*Cc];     // v in half
__device__ __half g_qh[(size_t)BQ*Cc];        // q in half
__device__ __half g_headsh[(size_t)BQ*256];   // sampled heads, half
__device__ float  g_qout[(size_t)BQ*384];     // fused [logits(128) | offsets(256)]
__device__ __half g_wqh[256*384];             // concat weights half
__device__ __half g_wvh[256*256];             // W_val half
__device__ __half g_woh[256*256];             // W_out half
__device__ float  g_bq[384];                  // concat bias

__device__ __forceinline__ uint32_t pack_h2(float a, float b) {
    __half2 t = __floats2half2_rn(a, b);
    return *reinterpret_cast<uint32_t*>(&t);
}
__device__ __forceinline__ void cp_async16(void* sdst, const void* gsrc) {
    uint32_t s = (uint32_t)__cvta_generic_to_shared(sdst);
    asm volatile("cp.async.cg.shared.global [%0], [%1], 16;" :: "r"(s), "l"(gsrc));
}
__device__ __forceinline__ void cp_commit() {
    asm volatile("cp.async.commit_group;");
}
template<int N>
__device__ __forceinline__ void cp_wait() {
    asm volatile("cp.async.wait_group %0;" :: "n"(N));
}

// ---------------------------------------------------------------------------
// Streaming fp32 -> fp16 conversion (vectorized). n4 = n/4.
// ---------------------------------------------------------------------------
__global__ void cvt_f2h(const float4* __restrict__ src, __half* __restrict__ dst,
                        int n4) {
    int i = blockIdx.x * blockDim.x + threadIdx.x;
    if (i < n4) {
        float4 v = src[i];
        *(uint2*)(dst + (size_t)i * 4) = make_uint2(pack_h2(v.x, v.y), pack_h2(v.z, v.w));
    }
}

// ---------------------------------------------------------------------------
// Weight prep: concat W_attn|W_off -> g_wqh (half), convert W_val/W_out,
// concat biases. <<<256, 384>>>
// ---------------------------------------------------------------------------
__global__ void prep_weights(const float* __restrict__ Wa, const float* __restrict__ Wo,
                             const float* __restrict__ ba, const float* __restrict__ bo,
                             const float* __restrict__ Wv, const float* __restrict__ Wu) {
    const int r = blockIdx.x;
    const int c = threadIdx.x;
    g_wqh[r * 384 + c] = __float2half((c < 128) ? Wa[r * 128 + c] : Wo[r * 256 + (c - 128)]);
    if (c < 256) {
        g_wvh[r * 256 + c] = __float2half(Wv[r * 256 + c]);
        g_woh[r * 256 + c] = __float2half(Wu[r * 256 + c]);
    }
    if (r == 0) g_bq[c] = (c < 128) ? ba[c] : bo[c - 128];
}

// ---------------------------------------------------------------------------
// fp16 tensor-core GEMM, cp.async double-buffered.
// C[Md,Nd] = A[Md,256] @ B[256,Nd] + bias[Nd];  A,B half in GMEM.
// BM=128, BN=128, BK=64. 256 threads = 8 warps (4 row x 2 col); warp 32x64
// via 2x4 wmma m16n16k16, fp32 accumulate. Bias preloaded into accumulators.
// STORE_MODE 0: fp32 row-major direct frag stores.
// STORE_MODE 1: fp16 permuted store -> g_vph[B,M,N,D] (staged via smem).
// ---------------------------------------------------------------------------
template<int STORE_MODE>
__global__ __launch_bounds__(256)
void gemm_h(const __half* __restrict__ A, const __half* __restrict__ Bm,
            const float* __restrict__ bias, float* __restrict__ Cd, int Nd) {
    constexpr int BM = 128, BN = 128, BK = 64;
    constexpr int AKp = 72;                 // A smem pitch (halves), 144B
    constexpr int BNp = 136;                // B smem pitch (halves), 272B
    constexpr int ASZH = BM * AKp;          // 9216 halves / stage
    constexpr int BSZH = BK * BNp;          // 8704 halves / stage

    extern __shared__ __align__(16) char smem[];
    __half* As[2] = { (__half*)smem, (__half*)smem + ASZH };
    __half* Bs[2] = { (__half*)smem + 2 * ASZH, (__half*)smem + 2 * ASZH + BSZH };
    float* biasS = (float*)(smem + (2 * ASZH + 2 * BSZH) * 2);  // 16 x BNp floats

    const int tid = threadIdx.x;
    const int wid = tid >> 5;
    const int warpRow = (wid >> 1) * 32;   // 0,32,64,96
    const int warpCol = (wid & 1) * 64;    // 0,64
    const int rowBase = blockIdx.y * BM;
    const int colBase = blockIdx.x * BN;

    // ---- bias -> replicated smem tile (16 rows) -> accumulators ----
    #pragma unroll
    for (int i = tid; i < 16 * BN; i += 256) {
        int r = i >> 7, c = i & 127;
        biasS[r * BNp + c] = bias[colBase + c];
    }
    __syncthreads();

    wmma::fragment<wmma::accumulator, 16, 16, 16, float> acc[2][4];
    #pragma unroll
    for (int i = 0; i < 2; i++)
        #pragma unroll
        for (int j = 0; j < 4; j++)
            wmma::load_matrix_sync(acc[i][j], &biasS[warpCol + j * 16], BNp,
                                   wmma::mem_row_major);
    __syncthreads();

    // ---- async load helpers: 4+4 cp.async 16B per thread per tile ----
    auto issue = [&](int st, int k0) {
        #pragma unroll
        for (int i = 0; i < 4; i++) {
            int idx = tid + i * 256;
            int r = idx >> 3, c8 = (idx & 7) * 8;
            cp_async16(&As[st][r * AKp + c8],
                       A + (size_t)(rowBase + r) * Cc + k0 + c8);
        }
        #pragma unroll
        for (int i = 0; i < 4; i++) {
            int idx = tid + i * 256;
            int r = idx >> 4, c8 = (idx & 15) * 8;
            cp_async16(&Bs[st][r * BNp + c8],
                       Bm + (size_t)(k0 + r) * Nd + colBase + c8);
        }
    };

    issue(0, 0);
    cp_commit();

    #pragma unroll
    for (int t = 0; t < 4; t++) {
        if (t < 3) { issue((t + 1) & 1, (t + 1) * BK); cp_commit(); cp_wait<1>(); }
        else cp_wait<0>();
        __syncthreads();

        const __half* Ab = As[t & 1];
        const __half* Bb = Bs[t & 1];
        #pragma unroll
        for (int kk = 0; kk < BK; kk += 16) {
            wmma::fragment<wmma::matrix_a, 16, 16, 16, __half, wmma::row_major> af[2];
            wmma::fragment<wmma::matrix_b, 16, 16, 16, __half, wmma::row_major> bf[4];
            #pragma unroll
            for (int i = 0; i < 2; i++)
                wmma::load_matrix_sync(af[i], &Ab[(warpRow + i * 16) * AKp + kk], AKp);
            #pragma unroll
            for (int j = 0; j < 4; j++)
                wmma::load_matrix_sync(bf[j], &Bb[kk * BNp + warpCol + j * 16], BNp);
            #pragma unroll
            for (int i = 0; i < 2; i++)
                #pragma unroll
                for (int j = 0; j < 4; j++)
                    wmma::mma_sync(acc[i][j], af[i], bf[j], acc[i][j]);
        }
        __syncthreads();
    }

    if (STORE_MODE == 0) {
        #pragma unroll
        for (int i = 0; i < 2; i++) {
            int row0 = rowBase + warpRow + i * 16;
            #pragma unroll
            for (int j = 0; j < 4; j++) {
                int col0 = colBase + warpCol + j * 16;
                wmma::store_matrix_sync(Cd + (size_t)row0 * Nd + col0, acc[i][j],
                                        Nd, wmma::mem_row_major);
            }
        }
    } else {
        // ---- staged fp16 permuted store -> g_vph, two 64-col passes ----
        constexpr int SP = 68;
        float* stage = (float*)smem;           // 128*68*4 = 34816 B (fits)
        #pragma unroll
        for (int pass = 0; pass < 2; pass++) {
            __syncthreads();
            if ((wid & 1) == pass) {
                #pragma unroll
                for (int i = 0; i < 2; i++)
                    #pragma unroll
                    for (int j = 0; j < 4; j++)
                        wmma::store_matrix_sync(&stage[(warpRow + i * 16) * SP + j * 16],
                                                acc[i][j], SP, wmma::mem_row_major);
            }
            __syncthreads();
            #pragma unroll
            for (int i = 0; i < 8; i++) {
                int idx = tid + i * 256;
                int r = idx >> 4, c4 = (idx & 15) * 4;
                float4 v = *(const float4*)&stage[r * SP + c4];
                int row0 = rowBase + r;
                int colG = colBase + pass * 64 + c4;
                int b = row0 / Nc, n = row0 - b * Nc;
                int m = colG >> 5, d = colG & 31;
                __half* ptr = g_vph + (((size_t)((b * Mh + m) * Nc) + n) << 5) + d;
                *(uint2*)ptr = make_uint2(pack_h2(v.x, v.y), pack_h2(v.z, v.w));
            }
        }
    }
}

// ---------------------------------------------------------------------------
// Warp-autonomous sampling: one warp per (b,q,head). Paired-corner __half2
// gathers; lanes 0-15 left corners, 16-31 right corners; xor-16 reduce.
// Writes heads as half.
// ---------------------------------------------------------------------------
__global__ void sample_kernel(const float* __restrict__ p,
                              const int* __restrict__ shapes,
                              const int* __restrict__ level_index) {
    const unsigned FULL = 0xffffffffu;
    const int w = (blockIdx.x * blockDim.x + threadIdx.x) >> 5;
    const int lane = threadIdx.x & 31;
    const int bq = w >> 3;
    const int m = w & 7;
    const int b = bq >> 12;

    const float offv = g_qout[bq * 384 + 128 + m * 32 + lane];

    float lg = (lane < 16) ? g_qout[bq * 384 + m * 16 + lane] : -1e30f;
    float mx = lg;
    #pragma unroll
    for (int s = 8; s; s >>= 1) mx = fmaxf(mx, __shfl_xor_sync(FULL, mx, s));
    float e = (lane < 16) ? __expf(lg - mx) : 0.f;
    float sum = e;
    #pragma unroll
    for (int s = 8; s; s >>= 1) sum += __shfl_xor_sync(FULL, sum, s);
    const float awv = e / sum;

    // per-(point, corner-group) precompute: lane = pt*2 + grp
    const int pt  = lane >> 1;
    const int grp = lane & 1;
    const int l = pt >> 2;
    const int H  = shapes[2*l + 0];
    const int Wd = shapes[2*l + 1];
    const float px = p[bq * 8 + 2*l + 0];
    const float py = p[bq * 8 + 2*l + 1];
    const int base = level_index[l];

    const float ox = __shfl_sync(FULL, offv, pt * 2);
    const float oy = __shfl_sync(FULL, offv, pt * 2 + 1);
    const float aw = __shfl_sync(FULL, awv, pt);

    const float x = fmaf(px, (float)Wd, ox) - 0.5f;
    const float y = fmaf(py, (float)H,  oy) - 0.5f;
    const float x0f = floorf(x), y0f = floorf(y);
    const float lx = x - x0f, ly = y - y0f;
    const int x0 = (int)x0f, y0 = (int)y0f;

    const bool inx0 = (unsigned)x0       < (unsigned)Wd;
    const bool inx1 = (unsigned)(x0 + 1) < (unsigned)Wd;
    const bool iny0 = (unsigned)y0       < (unsigned)H;
    const bool iny1 = (unsigned)(y0 + 1) < (unsigned)H;

    float w11 = aw * lx * ly;
    float w10 = aw * lx - w11;
    float w01 = aw * ly - w11;
    float w00 = aw - w10 - w01 - w11;
    w00 = (inx0 & iny0) ? w00 : 0.f;
    w10 = (inx1 & iny0) ? w10 : 0.f;
    w01 = (inx0 & iny1) ? w01 : 0.f;
    w11 = (inx1 & iny1) ? w11 : 0.f;

    const int x0c = min(max(x0, 0), Wd - 1);
    const int x1c = min(max(x0 + 1, 0), Wd - 1);
    const int y0c = min(max(y0, 0), H - 1);
    const int y1c = min(max(y0 + 1, 0), H - 1);
    const int i00 = base + y0c * Wd + x0c;
    const int dx  = x1c - x0c;
    const int dyW = (y1c - y0c) * Wd;

    const float wtop = grp ? w10 : w00;
    const float wbot = grp ? w11 : w01;
    const int   itop = i00 + dx * grp;
    const int   ibot = itop + dyW;

    const int myg = lane >> 4;
    const __half* __restrict__ vpb =
        g_vph + ((size_t)((b * Mh + m) * Nc) << 5) + (lane & 15) * 2;

    float accx = 0.f, accy = 0.f;
    #pragma unroll
    for (int qq = 0; qq < 16; qq++) {
        const int src = qq * 2 + myg;
        const float wt = __shfl_sync(FULL, wtop, src);
        const float wb = __shfl_sync(FULL, wbot, src);
        const int it = __shfl_sync(FULL, itop, src);
        const int ib = __shfl_sync(FULL, ibot, src);
        const float2 tv = __half22float2(*(const __half2*)(vpb + (it << 5)));
        const float2 bv = __half22float2(*(const __half2*)(vpb + (ib << 5)));
        accx = fmaf(wt, tv.x, fmaf(wb, bv.x, accx));
        accy = fmaf(wt, tv.y, fmaf(wb, bv.y, accy));
    }
    accx += __shfl_xor_sync(FULL, accx, 16);
    accy += __shfl_xor_sync(FULL, accy, 16);

    if (lane < 16)
        *(__half2*)(g_headsh + bq * 256 + m * 32 + lane * 2) =
            __floats2half2_rn(accx, accy);
}

// ---------------------------------------------------------------------------
extern "C" void kernel_launch(void* const* d_in, const int* in_sizes, int n_in,
                              void* d_out, int out_size) {
    const float* q       = (const float*)d_in[0];
    const float* p       = (const float*)d_in[1];
    const float* v       = (const float*)d_in[2];
    const int*   shapes  = (const int*)d_in[3];
    const int*   lvl_idx = (const int*)d_in[4];
    const float* W_off   = (const float*)d_in[5];
    const float* b_off   = (const float*)d_in[6];
    const float* W_attn  = (const float*)d_in[7];
    const float* b_attn  = (const float*)d_in[8];
    const float* W_val   = (const float*)d_in[9];
    const float* b_val   = (const float*)d_in[10];
    const float* W_out   = (const float*)d_in[11];
    const float* b_out   = (const float*)d_in[12];
    float* out = (float*)d_out;

    __half* vh;    cudaGetSymbolAddress((void**)&vh,    g_vh);
    __half* qh;    cudaGetSymbolAddress((void**)&qh,    g_qh);
    __half* headsh;cudaGetSymbolAddress((void**)&headsh,g_headsh);
    float*  qout;  cudaGetSymbolAddress((void**)&qout,  g_qout);
    __half* wqh;   cudaGetSymbolAddress((void**)&wqh,   g_wqh);
    __half* wvh;   cudaGetSymbolAddress((void**)&wvh,   g_wvh);
    __half* woh;   cudaGetSymbolAddress((void**)&woh,   g_woh);
    float*  bqv;   cudaGetSymbolAddress((void**)&bqv,   g_bq);

    // smem: 2 stages * (A 18432B + B 17408B) + bias 8704B = 80384 B
    const int smemB = 2 * (128 * 72 * 2 + 64 * 136 * 2) + 16 * 136 * 4;
    cudaFuncSetAttribute(gemm_h<0>, cudaFuncAttributeMaxDynamicSharedMemorySize, smemB);
    cudaFuncSetAttribute(gemm_h<1>, cudaFuncAttributeMaxDynamicSharedMemorySize, smemB);

    // 0) conversions + weight prep
    cvt_f2h<<<(Bc * Nc * Cc / 4 + 255) / 256, 256>>>((const float4*)v, vh, Bc * Nc * Cc / 4);
    cvt_f2h<<<(BQ * Cc / 4 + 255) / 256, 256>>>((const float4*)q, qh, BQ * Cc / 4);
    prep_weights<<<256, 384>>>(W_attn, W_off, b_attn, b_off, W_val, W_out);

    // 1) value projection: [B*N,256] @ [256,256] -> g_vph (head-major fp16)
    {
        dim3 grid(Cc / 128, (Bc * Nc) / 128);   // (2, 680)
        gemm_h<1><<<grid, 256, smemB>>>(vh, wvh, b_val, nullptr, Cc);
    }
    // 2) fused logits+offsets: [BQ,256] @ [256,384] -> g_qout fp32
    {
        dim3 grid(384 / 128, BQ / 128);         // (3, 128)
        gemm_h<0><<<grid, 256, smemB>>>(qh, wqh, bqv, qout, 384);
    }
    // 3) softmax + bilinear sampling -> g_headsh (half)
    sample_kernel<<<(BQ * Mh) / 8, 256>>>(p, shapes, lvl_idx);
    // 4) output projection: [BQ,256] @ [256,256] -> d_out fp32
    {
        dim3 grid(Cc / 128, BQ / 128);          // (2, 128)
        gemm_h<0><<<grid, 256, smemB>>>(headsh, woh, b_out, out, Cc);
    }
}

// round 8
// speedup vs baseline: 2.6017x; 1.0068x over previous
#include <cuda_runtime.h>
#include <cuda_fp16.h>
#include <mma.h>
#include <cstdint>

using namespace nvcuda;

// Problem constants (fixed by the dataset)
#define Bc 4
#define Qc 4096
#define Cc 256
#define Mh 8
#define Lc 4
#define Pc 4
#define Dc 32
#define Nc 21760
#define BQ (Bc*Qc)          // 16384

// Scratch (device globals; allocation-free rule)
__device__ __half g_vph[(size_t)Bc*Mh*Nc*Dc]; // [B,M,N,D] head-major vproj, fp16
__device__ __half g_vh[(size_t)Bc*Nc*Cc];     // v in half
__device__ __half g_qh[(size_t)BQ*Cc];        // q in half
__device__ __half g_headsh[(size_t)BQ*256];   // sampled heads, half
__device__ float  g_qout[(size_t)BQ*384];     // fused [logits(128) | offsets(256)]
__device__ __half g_wqh[256*384];             // concat weights half
__device__ __half g_wvh[256*256];             // W_val half
__device__ __half g_woh[256*256];             // W_out half
__device__ float  g_bq[384];                  // concat bias

__device__ __forceinline__ uint32_t pack_h2(float a, float b) {
    __half2 t = __floats2half2_rn(a, b);
    return *reinterpret_cast<uint32_t*>(&t);
}
__device__ __forceinline__ void cp_async16(void* sdst, const void* gsrc) {
    uint32_t s = (uint32_t)__cvta_generic_to_shared(sdst);
    asm volatile("cp.async.cg.shared.global [%0], [%1], 16;" :: "r"(s), "l"(gsrc));
}
__device__ __forceinline__ void cp_commit() {
    asm volatile("cp.async.commit_group;");
}
template<int N>
__device__ __forceinline__ void cp_wait() {
    asm volatile("cp.async.wait_group %0;" :: "n"(N));
}

// ---------------------------------------------------------------------------
// Streaming fp32 -> fp16 conversion (vectorized). n4 = n/4.
// ---------------------------------------------------------------------------
__global__ void cvt_f2h(const float4* __restrict__ src, __half* __restrict__ dst,
                        int n4) {
    int i = blockIdx.x * blockDim.x + threadIdx.x;
    if (i < n4) {
        float4 v = src[i];
        *(uint2*)(dst + (size_t)i * 4) = make_uint2(pack_h2(v.x, v.y), pack_h2(v.z, v.w));
    }
}

// ---------------------------------------------------------------------------
// Weight prep: concat W_attn|W_off -> g_wqh (half), convert W_val/W_out,
// concat biases. <<<256, 384>>>
// ---------------------------------------------------------------------------
__global__ void prep_weights(const float* __restrict__ Wa, const float* __restrict__ Wo,
                             const float* __restrict__ ba, const float* __restrict__ bo,
                             const float* __restrict__ Wv, const float* __restrict__ Wu) {
    const int r = blockIdx.x;
    const int c = threadIdx.x;
    g_wqh[r * 384 + c] = __float2half((c < 128) ? Wa[r * 128 + c] : Wo[r * 256 + (c - 128)]);
    if (c < 256) {
        g_wvh[r * 256 + c] = __float2half(Wv[r * 256 + c]);
        g_woh[r * 256 + c] = __float2half(Wu[r * 256 + c]);
    }
    if (r == 0) g_bq[c] = (c < 128) ? ba[c] : bo[c - 128];
}

// ---------------------------------------------------------------------------
// fp16 tensor-core GEMM, cp.async double-buffered, 2 CTAs/SM.
// C[Md,Nd] = A[Md,256] @ B[256,Nd] + bias[Nd];  A,B half in GMEM.
// BM=128, BN=64, BK=64. 256 threads = 8 warps (4 row x 2 col); each warp
// 32x32 via 2x2 wmma m16n16k16 frags, fp32 accumulate.
// STORE_MODE 0: fp32 row-major direct frag stores.
// STORE_MODE 1: fp16 permuted store -> g_vph[B,M,N,D] (staged via smem).
// ---------------------------------------------------------------------------
template<int STORE_MODE>
__global__ __launch_bounds__(256, 2)
void gemm_h(const __half* __restrict__ A, const __half* __restrict__ Bm,
            const float* __restrict__ bias, float* __restrict__ Cd, int Nd) {
    constexpr int BM = 128, BN = 64, BK = 64;
    constexpr int AKp = 72;                 // A smem pitch (halves)
    constexpr int BNp = 72;                 // B smem pitch (halves)
    constexpr int ASZH = BM * AKp;          // 9216 halves / stage
    constexpr int BSZH = BK * BNp;          // 4608 halves / stage

    extern __shared__ __align__(16) char smem[];
    __half* As[2] = { (__half*)smem, (__half*)smem + ASZH };
    __half* Bs[2] = { (__half*)smem + 2 * ASZH, (__half*)smem + 2 * ASZH + BSZH };
    float* biasS = (float*)(smem + (2 * ASZH + 2 * BSZH) * 2);  // 16 x BNp floats

    const int tid = threadIdx.x;
    const int wid = tid >> 5;
    const int warpRow = (wid >> 1) * 32;   // 0,32,64,96
    const int warpCol = (wid & 1) * 32;    // 0,32
    const int rowBase = blockIdx.y * BM;
    const int colBase = blockIdx.x * BN;

    // ---- bias -> replicated smem tile (16 rows) -> accumulators ----
    #pragma unroll
    for (int i = tid; i < 16 * BN; i += 256) {
        int r = i >> 6, c = i & 63;
        biasS[r * BNp + c] = bias[colBase + c];
    }
    __syncthreads();

    wmma::fragment<wmma::accumulator, 16, 16, 16, float> acc[2][2];
    #pragma unroll
    for (int i = 0; i < 2; i++)
        #pragma unroll
        for (int j = 0; j < 2; j++)
            wmma::load_matrix_sync(acc[i][j], &biasS[warpCol + j * 16], BNp,
                                   wmma::mem_row_major);
    __syncthreads();

    // ---- async loads: A 4x16B, B 2x16B per thread per tile ----
    auto issue = [&](int st, int k0) {
        #pragma unroll
        for (int i = 0; i < 4; i++) {
            int idx = tid + i * 256;
            int r = idx >> 3, c8 = (idx & 7) * 8;
            cp_async16(&As[st][r * AKp + c8],
                       A + (size_t)(rowBase + r) * Cc + k0 + c8);
        }
        #pragma unroll
        for (int i = 0; i < 2; i++) {
            int idx = tid + i * 256;
            int r = idx >> 3, c8 = (idx & 7) * 8;
            cp_async16(&Bs[st][r * BNp + c8],
                       Bm + (size_t)(k0 + r) * Nd + colBase + c8);
        }
    };

    issue(0, 0);
    cp_commit();

    #pragma unroll
    for (int t = 0; t < 4; t++) {
        if (t < 3) { issue((t + 1) & 1, (t + 1) * BK); cp_commit(); cp_wait<1>(); }
        else cp_wait<0>();
        __syncthreads();

        const __half* Ab = As[t & 1];
        const __half* Bb = Bs[t & 1];
        #pragma unroll
        for (int kk = 0; kk < BK; kk += 16) {
            wmma::fragment<wmma::matrix_a, 16, 16, 16, __half, wmma::row_major> af[2];
            wmma::fragment<wmma::matrix_b, 16, 16, 16, __half, wmma::row_major> bf[2];
            #pragma unroll
            for (int i = 0; i < 2; i++)
                wmma::load_matrix_sync(af[i], &Ab[(warpRow + i * 16) * AKp + kk], AKp);
            #pragma unroll
            for (int j = 0; j < 2; j++)
                wmma::load_matrix_sync(bf[j], &Bb[kk * BNp + warpCol + j * 16], BNp);
            #pragma unroll
            for (int i = 0; i < 2; i++)
                #pragma unroll
                for (int j = 0; j < 2; j++)
                    wmma::mma_sync(acc[i][j], af[i], bf[j], acc[i][j]);
        }
        __syncthreads();
    }

    if (STORE_MODE == 0) {
        #pragma unroll
        for (int i = 0; i < 2; i++) {
            int row0 = rowBase + warpRow + i * 16;
            #pragma unroll
            for (int j = 0; j < 2; j++) {
                int col0 = colBase + warpCol + j * 16;
                wmma::store_matrix_sync(Cd + (size_t)row0 * Nd + col0, acc[i][j],
                                        Nd, wmma::mem_row_major);
            }
        }
    } else {
        // ---- staged fp16 permuted store -> g_vph (single pass) ----
        constexpr int SP = 68;
        float* stage = (float*)smem;           // 128*68*4 = 34816 B (fits)
        __syncthreads();
        #pragma unroll
        for (int i = 0; i < 2; i++)
            #pragma unroll
            for (int j = 0; j < 2; j++)
                wmma::store_matrix_sync(&stage[(warpRow + i * 16) * SP + warpCol + j * 16],
                                        acc[i][j], SP, wmma::mem_row_major);
        __syncthreads();
        // 128 rows x 64 cols -> half, permuted. 2048 float4-reads, 8/thread.
        #pragma unroll
        for (int i = 0; i < 8; i++) {
            int idx = tid + i * 256;
            int r = idx >> 4, c4 = (idx & 15) * 4;
            float4 v = *(const float4*)&stage[r * SP + c4];
            int row0 = rowBase + r;
            int colG = colBase + c4;
            int b = row0 / Nc, n = row0 - b * Nc;
            int m = colG >> 5, d = colG & 31;
            __half* ptr = g_vph + (((size_t)((b * Mh + m) * Nc) + n) << 5) + d;
            *(uint2*)ptr = make_uint2(pack_h2(v.x, v.y), pack_h2(v.z, v.w));
        }
    }
}

// ---------------------------------------------------------------------------
// Warp-autonomous sampling: one warp per (b,q,head). Paired-corner __half2
// gathers; lanes 0-15 left corners, 16-31 right corners; xor-16 reduce.
// Writes heads as half.
// ---------------------------------------------------------------------------
__global__ void sample_kernel(const float* __restrict__ p,
                              const int* __restrict__ shapes,
                              const int* __restrict__ level_index) {
    const unsigned FULL = 0xffffffffu;
    const int w = (blockIdx.x * blockDim.x + threadIdx.x) >> 5;
    const int lane = threadIdx.x & 31;
    const int bq = w >> 3;
    const int m = w & 7;
    const int b = bq >> 12;

    const float offv = g_qout[bq * 384 + 128 + m * 32 + lane];

    float lg = (lane < 16) ? g_qout[bq * 384 + m * 16 + lane] : -1e30f;
    float mx = lg;
    #pragma unroll
    for (int s = 8; s; s >>= 1) mx = fmaxf(mx, __shfl_xor_sync(FULL, mx, s));
    float e = (lane < 16) ? __expf(lg - mx) : 0.f;
    float sum = e;
    #pragma unroll
    for (int s = 8; s; s >>= 1) sum += __shfl_xor_sync(FULL, sum, s);
    const float awv = e / sum;

    // per-(point, corner-group) precompute: lane = pt*2 + grp
    const int pt  = lane >> 1;
    const int grp = lane & 1;
    const int l = pt >> 2;
    const int H  = shapes[2*l + 0];
    const int Wd = shapes[2*l + 1];
    const float px = p[bq * 8 + 2*l + 0];
    const float py = p[bq * 8 + 2*l + 1];
    const int base = level_index[l];

    const float ox = __shfl_sync(FULL, offv, pt * 2);
    const float oy = __shfl_sync(FULL, offv, pt * 2 + 1);
    const float aw = __shfl_sync(FULL, awv, pt);

    const float x = fmaf(px, (float)Wd, ox) - 0.5f;
    const float y = fmaf(py, (float)H,  oy) - 0.5f;
    const float x0f = floorf(x), y0f = floorf(y);
    const float lx = x - x0f, ly = y - y0f;
    const int x0 = (int)x0f, y0 = (int)y0f;

    const bool inx0 = (unsigned)x0       < (unsigned)Wd;
    const bool inx1 = (unsigned)(x0 + 1) < (unsigned)Wd;
    const bool iny0 = (unsigned)y0       < (unsigned)H;
    const bool iny1 = (unsigned)(y0 + 1) < (unsigned)H;

    float w11 = aw * lx * ly;
    float w10 = aw * lx - w11;
    float w01 = aw * ly - w11;
    float w00 = aw - w10 - w01 - w11;
    w00 = (inx0 & iny0) ? w00 : 0.f;
    w10 = (inx1 & iny0) ? w10 : 0.f;
    w01 = (inx0 & iny1) ? w01 : 0.f;
    w11 = (inx1 & iny1) ? w11 : 0.f;

    const int x0c = min(max(x0, 0), Wd - 1);
    const int x1c = min(max(x0 + 1, 0), Wd - 1);
    const int y0c = min(max(y0, 0), H - 1);
    const int y1c = min(max(y0 + 1, 0), H - 1);
    const int i00 = base + y0c * Wd + x0c;
    const int dx  = x1c - x0c;
    const int dyW = (y1c - y0c) * Wd;

    const float wtop = grp ? w10 : w00;
    const float wbot = grp ? w11 : w01;
    const int   itop = i00 + dx * grp;
    const int   ibot = itop + dyW;

    const int myg = lane >> 4;
    const __half* __restrict__ vpb =
        g_vph + ((size_t)((b * Mh + m) * Nc) << 5) + (lane & 15) * 2;

    float accx = 0.f, accy = 0.f;
    #pragma unroll
    for (int qq = 0; qq < 16; qq++) {
        const int src = qq * 2 + myg;
        const float wt = __shfl_sync(FULL, wtop, src);
        const float wb = __shfl_sync(FULL, wbot, src);
        const int it = __shfl_sync(FULL, itop, src);
        const int ib = __shfl_sync(FULL, ibot, src);
        const float2 tv = __half22float2(*(const __half2*)(vpb + (it << 5)));
        const float2 bv = __half22float2(*(const __half2*)(vpb + (ib << 5)));
        accx = fmaf(wt, tv.x, fmaf(wb, bv.x, accx));
        accy = fmaf(wt, tv.y, fmaf(wb, bv.y, accy));
    }
    accx += __shfl_xor_sync(FULL, accx, 16);
    accy += __shfl_xor_sync(FULL, accy, 16);

    if (lane < 16)
        *(__half2*)(g_headsh + bq * 256 + m * 32 + lane * 2) =
            __floats2half2_rn(accx, accy);
}

// ---------------------------------------------------------------------------
extern "C" void kernel_launch(void* const* d_in, const int* in_sizes, int n_in,
                              void* d_out, int out_size) {
    const float* q       = (const float*)d_in[0];
    const float* p       = (const float*)d_in[1];
    const float* v       = (const float*)d_in[2];
    const int*   shapes  = (const int*)d_in[3];
    const int*   lvl_idx = (const int*)d_in[4];
    const float* W_off   = (const float*)d_in[5];
    const float* b_off   = (const float*)d_in[6];
    const float* W_attn  = (const float*)d_in[7];
    const float* b_attn  = (const float*)d_in[8];
    const float* W_val   = (const float*)d_in[9];
    const float* b_val   = (const float*)d_in[10];
    const float* W_out   = (const float*)d_in[11];
    const float* b_out   = (const float*)d_in[12];
    float* out = (float*)d_out;

    __half* vh;    cudaGetSymbolAddress((void**)&vh,    g_vh);
    __half* qh;    cudaGetSymbolAddress((void**)&qh,    g_qh);
    __half* headsh;cudaGetSymbolAddress((void**)&headsh,g_headsh);
    float*  qout;  cudaGetSymbolAddress((void**)&qout,  g_qout);
    __half* wqh;   cudaGetSymbolAddress((void**)&wqh,   g_wqh);
    __half* wvh;   cudaGetSymbolAddress((void**)&wvh,   g_wvh);
    __half* woh;   cudaGetSymbolAddress((void**)&woh,   g_woh);
    float*  bqv;   cudaGetSymbolAddress((void**)&bqv,   g_bq);

    // smem: 2 stages * (A 18432B + B 9216B) + bias 16*72*4 = 59904 B
    const int smemB = 2 * (128 * 72 * 2 + 64 * 72 * 2) + 16 * 72 * 4;
    cudaFuncSetAttribute(gemm_h<0>, cudaFuncAttributeMaxDynamicSharedMemorySize, smemB);
    cudaFuncSetAttribute(gemm_h<1>, cudaFuncAttributeMaxDynamicSharedMemorySize, smemB);

    // 0) conversions + weight prep
    cvt_f2h<<<(Bc * Nc * Cc / 4 + 255) / 256, 256>>>((const float4*)v, vh, Bc * Nc * Cc / 4);
    cvt_f2h<<<(BQ * Cc / 4 + 255) / 256, 256>>>((const float4*)q, qh, BQ * Cc / 4);
    prep_weights<<<256, 384>>>(W_attn, W_off, b_attn, b_off, W_val, W_out);

    // 1) value projection: [B*N,256] @ [256,256] -> g_vph (head-major fp16)
    {
        dim3 grid(Cc / 64, (Bc * Nc) / 128);    // (4, 680)
        gemm_h<1><<<grid, 256, smemB>>>(vh, wvh, b_val, nullptr, Cc);
    }
    // 2) fused logits+offsets: [BQ,256] @ [256,384] -> g_qout fp32
    {
        dim3 grid(384 / 64, BQ / 128);          // (6, 128)
        gemm_h<0><<<grid, 256, smemB>>>(qh, wqh, bqv, qout, 384);
    }
    // 3) softmax + bilinear sampling -> g_headsh (half)
    sample_kernel<<<(BQ * Mh) / 8, 256>>>(p, shapes, lvl_idx);
    // 4) output projection: [BQ,256] @ [256,256] -> d_out fp32
    {
        dim3 grid(Cc / 64, BQ / 128);           // (4, 128)
        gemm_h<0><<<grid, 256, smemB>>>(headsh, woh, b_out, out, Cc);
    }
}